// round 6
// baseline (speedup 1.0000x reference)
#include <cuda_runtime.h>
#include <cuda_bf16.h>

// VariableGroupNorm: N=32, C=256, H=W=56, G=32, ragged groups (4/12 channels).
// One CTA per (n, g); group data is a contiguous span (12.25 KB..147 KB).
// R5 measured: x4 MLP raised DRAM 49.7->57.9% but regs=40 cut residency to
// 6 CTAs/SM (occ 53%). This version fixes both factors:
//   TPB=128  -> all 1024 CTAs resident in ONE wave (<=8 CTAs/SM @ 64 regs),
//   pass 1 x8 load batch (8 independent LDG.128 in flight per warp, only 4
//   accumulator pairs). Pass 2: x4, streaming loads (last use) + streaming
//   stores (write-only out must not evict x from L2).
// Min DRAM traffic: 205.5 MB -> ~31 us floor at ~6.6 TB/s.

#define NGROUPS 32
#define NCHAN   256
#define HW      3136
#define HW4     784      // HW / 4
#define EPSV    1e-5f
#define TPB     128

__global__ __launch_bounds__(TPB, 8)
void vgn_fused_kernel(const float* __restrict__ x,
                      const float* __restrict__ gamma,
                      const float* __restrict__ beta,
                      const int*   __restrict__ gs_raw,
                      float* __restrict__ out)
{
    __shared__ int   s_off;
    __shared__ int   s_cnt;
    __shared__ float s_red[8];
    __shared__ float s_scale;
    __shared__ float s_shift;

    // Big-groups-first schedule (insurance if residency drops below 7/SM):
    // alternating sizes [4,12,...] -> odd g are heavy. First half of bids -> odd g.
    const int b    = blockIdx.x;
    const int half = gridDim.x >> 1;
    int n, g;
    if (b < half) { n = b / (NGROUPS / 2);  g = (((b % (NGROUPS / 2)) << 1) | 1); }
    else          { const int b2 = b - half;
                    n = b2 / (NGROUPS / 2); g = ((b2 % (NGROUPS / 2)) << 1); }

    if (threadIdx.x == 0) {
        // Dtype hedge: group_sizes may land as int32 or int64 (low words).
        int sum1 = 0;
        #pragma unroll
        for (int i = 0; i < NGROUPS; ++i) sum1 += gs_raw[i];
        const int stride = (sum1 == NCHAN) ? 1 : 2;
        int off = 0;
        for (int i = 0; i < g; ++i) off += gs_raw[i * stride];
        s_off = off;
        s_cnt = gs_raw[g * stride];
    }
    __syncthreads();

    const int c0 = s_off;
    const int cs = s_cnt;
    const size_t base = (size_t)(n * NCHAN + c0) * HW;
    const float4* __restrict__ xb = reinterpret_cast<const float4*>(x + base);
    float4* __restrict__       ob = reinterpret_cast<float4*>(out + base);
    const int nvec = cs * HW4;  // float4 count for this group

    // ---- Pass 1: sum / sumsq, x8 load batch, 4 accumulator pairs ----
    float s0 = 0.f, s1 = 0.f, s2 = 0.f, s3 = 0.f;
    float q0 = 0.f, q1 = 0.f, q2 = 0.f, q3 = 0.f;

    int i = threadIdx.x;
    for (; i + 7 * TPB < nvec; i += 8 * TPB) {
        const float4 v0 = __ldg(&xb[i]);
        const float4 v1 = __ldg(&xb[i + TPB]);
        const float4 v2 = __ldg(&xb[i + 2 * TPB]);
        const float4 v3 = __ldg(&xb[i + 3 * TPB]);
        const float4 v4 = __ldg(&xb[i + 4 * TPB]);
        const float4 v5 = __ldg(&xb[i + 5 * TPB]);
        const float4 v6 = __ldg(&xb[i + 6 * TPB]);
        const float4 v7 = __ldg(&xb[i + 7 * TPB]);
        s0 += (v0.x + v0.y) + (v0.z + v0.w);
        q0 += (v0.x * v0.x + v0.y * v0.y) + (v0.z * v0.z + v0.w * v0.w);
        s1 += (v1.x + v1.y) + (v1.z + v1.w);
        q1 += (v1.x * v1.x + v1.y * v1.y) + (v1.z * v1.z + v1.w * v1.w);
        s2 += (v2.x + v2.y) + (v2.z + v2.w);
        q2 += (v2.x * v2.x + v2.y * v2.y) + (v2.z * v2.z + v2.w * v2.w);
        s3 += (v3.x + v3.y) + (v3.z + v3.w);
        q3 += (v3.x * v3.x + v3.y * v3.y) + (v3.z * v3.z + v3.w * v3.w);
        s0 += (v4.x + v4.y) + (v4.z + v4.w);
        q0 += (v4.x * v4.x + v4.y * v4.y) + (v4.z * v4.z + v4.w * v4.w);
        s1 += (v5.x + v5.y) + (v5.z + v5.w);
        q1 += (v5.x * v5.x + v5.y * v5.y) + (v5.z * v5.z + v5.w * v5.w);
        s2 += (v6.x + v6.y) + (v6.z + v6.w);
        q2 += (v6.x * v6.x + v6.y * v6.y) + (v6.z * v6.z + v6.w * v6.w);
        s3 += (v7.x + v7.y) + (v7.z + v7.w);
        q3 += (v7.x * v7.x + v7.y * v7.y) + (v7.z * v7.z + v7.w * v7.w);
    }
    for (; i < nvec; i += TPB) {
        const float4 a = __ldg(&xb[i]);
        s0 += (a.x + a.y) + (a.z + a.w);
        q0 += (a.x * a.x + a.y * a.y) + (a.z * a.z + a.w * a.w);
    }
    float s  = (s0 + s1) + (s2 + s3);
    float sq = (q0 + q1) + (q2 + q3);

    // warp reduce
    #pragma unroll
    for (int o = 16; o > 0; o >>= 1) {
        s  += __shfl_xor_sync(0xffffffffu, s,  o);
        sq += __shfl_xor_sync(0xffffffffu, sq, o);
    }
    const int wid = threadIdx.x >> 5;
    const int lid = threadIdx.x & 31;
    if (lid == 0) { s_red[wid] = s; s_red[4 + wid] = sq; }
    __syncthreads();

    if (threadIdx.x == 0) {
        float ts = 0.0f, tq = 0.0f;
        #pragma unroll
        for (int w = 0; w < TPB / 32; ++w) { ts += s_red[w]; tq += s_red[4 + w]; }
        const float cnt  = (float)cs * (float)HW;
        const float mean = ts / cnt;
        const float var  = tq / cnt - mean * mean;
        const float sc   = gamma[g] * rsqrtf(var + EPSV);
        s_scale = sc;
        s_shift = beta[g] - mean * sc;
    }
    __syncthreads();

    const float sc = s_scale;
    const float sh = s_shift;

    // ---- Pass 2: apply, x4; streaming loads (last use of x lines),
    // streaming stores (write-only out must not evict x from L2). ----
    i = threadIdx.x;
    for (; i + 3 * TPB < nvec; i += 4 * TPB) {
        float4 a = __ldcs(&xb[i]);
        float4 bb = __ldcs(&xb[i + TPB]);
        float4 c = __ldcs(&xb[i + 2 * TPB]);
        float4 d = __ldcs(&xb[i + 3 * TPB]);
        a.x = fmaf(a.x, sc, sh); a.y = fmaf(a.y, sc, sh);
        a.z = fmaf(a.z, sc, sh); a.w = fmaf(a.w, sc, sh);
        bb.x = fmaf(bb.x, sc, sh); bb.y = fmaf(bb.y, sc, sh);
        bb.z = fmaf(bb.z, sc, sh); bb.w = fmaf(bb.w, sc, sh);
        c.x = fmaf(c.x, sc, sh); c.y = fmaf(c.y, sc, sh);
        c.z = fmaf(c.z, sc, sh); c.w = fmaf(c.w, sc, sh);
        d.x = fmaf(d.x, sc, sh); d.y = fmaf(d.y, sc, sh);
        d.z = fmaf(d.z, sc, sh); d.w = fmaf(d.w, sc, sh);
        __stcs(&ob[i], a);
        __stcs(&ob[i + TPB], bb);
        __stcs(&ob[i + 2 * TPB], c);
        __stcs(&ob[i + 3 * TPB], d);
    }
    for (; i < nvec; i += TPB) {
        float4 a = __ldcs(&xb[i]);
        a.x = fmaf(a.x, sc, sh); a.y = fmaf(a.y, sc, sh);
        a.z = fmaf(a.z, sc, sh); a.w = fmaf(a.w, sc, sh);
        __stcs(&ob[i], a);
    }
}

extern "C" void kernel_launch(void* const* d_in, const int* in_sizes, int n_in,
                              void* d_out, int out_size)
{
    const float* x     = (const float*)d_in[0];
    const float* gamma = (const float*)d_in[1];
    const float* beta  = (const float*)d_in[2];
    const int*   gs    = (const int*)d_in[3];
    float*       out   = (float*)d_out;

    const int nbatch  = in_sizes[0] / (NCHAN * HW);  // 32
    const int nblocks = nbatch * NGROUPS;            // 1024

    vgn_fused_kernel<<<nblocks, TPB>>>(x, gamma, beta, gs, out);
}

// round 7
// speedup vs baseline: 1.0656x; 1.0656x over previous
#include <cuda_runtime.h>
#include <cuda_bf16.h>

// VariableGroupNorm: N=32, C=256, H=W=56, G=32, ragged groups (4/12 channels).
// One CTA per (n, g); group data is a contiguous span (12.25 KB..147 KB).
// Empirical gradient (R2/R5/R6): DRAM% tracks warps/SM x MLP/warp, but only
// when warp count stays high (R6: 18 warps x MLP8 regressed vs R5's 34 x 4).
// This round grows BOTH: TPB=256 with launch_bounds(256,5) pins 5 CTAs/SM
// (40 warps) and pass 1 uses an x6 load batch (6 LDG.128 in flight/warp,
// ~44 live regs <= 51 cap). Pass 2: x4, streaming loads (last use) +
// streaming stores (write-only out must not evict x from L2).
// Big-groups-first CTA order tames the 3:1 ragged-cost tail.
// Min DRAM traffic: 205.5 MB -> ~29 us floor at ~7 TB/s.

#define NGROUPS 32
#define NCHAN   256
#define HW      3136
#define HW4     784      // HW / 4
#define EPSV    1e-5f
#define TPB     256

__global__ __launch_bounds__(TPB, 5)
void vgn_fused_kernel(const float* __restrict__ x,
                      const float* __restrict__ gamma,
                      const float* __restrict__ beta,
                      const int*   __restrict__ gs_raw,
                      float* __restrict__ out)
{
    __shared__ int   s_off;
    __shared__ int   s_cnt;
    __shared__ float s_red[16];
    __shared__ float s_scale;
    __shared__ float s_shift;

    // Big-groups-first schedule: alternating sizes [4,12,...] -> odd g heavy.
    const int b    = blockIdx.x;
    const int half = gridDim.x >> 1;
    int n, g;
    if (b < half) { n = b / (NGROUPS / 2);  g = (((b % (NGROUPS / 2)) << 1) | 1); }
    else          { const int b2 = b - half;
                    n = b2 / (NGROUPS / 2); g = ((b2 % (NGROUPS / 2)) << 1); }

    if (threadIdx.x == 0) {
        // Dtype hedge: group_sizes may land as int32 or int64 (low words).
        int sum1 = 0;
        #pragma unroll
        for (int i = 0; i < NGROUPS; ++i) sum1 += gs_raw[i];
        const int stride = (sum1 == NCHAN) ? 1 : 2;
        int off = 0;
        for (int i = 0; i < g; ++i) off += gs_raw[i * stride];
        s_off = off;
        s_cnt = gs_raw[g * stride];
    }
    __syncthreads();

    const int c0 = s_off;
    const int cs = s_cnt;
    const size_t base = (size_t)(n * NCHAN + c0) * HW;
    const float4* __restrict__ xb = reinterpret_cast<const float4*>(x + base);
    float4* __restrict__       ob = reinterpret_cast<float4*>(out + base);
    const int nvec = cs * HW4;  // float4 count for this group

    // ---- Pass 1: sum / sumsq, x6 load batch, 3 accumulator pairs ----
    float s0 = 0.f, s1 = 0.f, s2 = 0.f;
    float q0 = 0.f, q1 = 0.f, q2 = 0.f;

    int i = threadIdx.x;
    for (; i + 5 * TPB < nvec; i += 6 * TPB) {
        const float4 v0 = __ldg(&xb[i]);
        const float4 v1 = __ldg(&xb[i + TPB]);
        const float4 v2 = __ldg(&xb[i + 2 * TPB]);
        const float4 v3 = __ldg(&xb[i + 3 * TPB]);
        const float4 v4 = __ldg(&xb[i + 4 * TPB]);
        const float4 v5 = __ldg(&xb[i + 5 * TPB]);
        s0 += (v0.x + v0.y) + (v0.z + v0.w);
        q0 += (v0.x * v0.x + v0.y * v0.y) + (v0.z * v0.z + v0.w * v0.w);
        s1 += (v1.x + v1.y) + (v1.z + v1.w);
        q1 += (v1.x * v1.x + v1.y * v1.y) + (v1.z * v1.z + v1.w * v1.w);
        s2 += (v2.x + v2.y) + (v2.z + v2.w);
        q2 += (v2.x * v2.x + v2.y * v2.y) + (v2.z * v2.z + v2.w * v2.w);
        s0 += (v3.x + v3.y) + (v3.z + v3.w);
        q0 += (v3.x * v3.x + v3.y * v3.y) + (v3.z * v3.z + v3.w * v3.w);
        s1 += (v4.x + v4.y) + (v4.z + v4.w);
        q1 += (v4.x * v4.x + v4.y * v4.y) + (v4.z * v4.z + v4.w * v4.w);
        s2 += (v5.x + v5.y) + (v5.z + v5.w);
        q2 += (v5.x * v5.x + v5.y * v5.y) + (v5.z * v5.z + v5.w * v5.w);
    }
    for (; i < nvec; i += TPB) {
        const float4 a = __ldg(&xb[i]);
        s0 += (a.x + a.y) + (a.z + a.w);
        q0 += (a.x * a.x + a.y * a.y) + (a.z * a.z + a.w * a.w);
    }
    float s  = s0 + (s1 + s2);
    float sq = q0 + (q1 + q2);

    // warp reduce
    #pragma unroll
    for (int o = 16; o > 0; o >>= 1) {
        s  += __shfl_xor_sync(0xffffffffu, s,  o);
        sq += __shfl_xor_sync(0xffffffffu, sq, o);
    }
    const int wid = threadIdx.x >> 5;
    const int lid = threadIdx.x & 31;
    if (lid == 0) { s_red[wid] = s; s_red[8 + wid] = sq; }
    __syncthreads();

    if (threadIdx.x == 0) {
        float ts = 0.0f, tq = 0.0f;
        #pragma unroll
        for (int w = 0; w < TPB / 32; ++w) { ts += s_red[w]; tq += s_red[8 + w]; }
        const float cnt  = (float)cs * (float)HW;
        const float mean = ts / cnt;
        const float var  = tq / cnt - mean * mean;
        const float sc   = gamma[g] * rsqrtf(var + EPSV);
        s_scale = sc;
        s_shift = beta[g] - mean * sc;
    }
    __syncthreads();

    const float sc = s_scale;
    const float sh = s_shift;

    // ---- Pass 2: apply, x4; streaming loads (last use of x lines),
    // streaming stores (write-only out must not evict x from L2). ----
    i = threadIdx.x;
    for (; i + 3 * TPB < nvec; i += 4 * TPB) {
        float4 a = __ldcs(&xb[i]);
        float4 bb = __ldcs(&xb[i + TPB]);
        float4 c = __ldcs(&xb[i + 2 * TPB]);
        float4 d = __ldcs(&xb[i + 3 * TPB]);
        a.x = fmaf(a.x, sc, sh); a.y = fmaf(a.y, sc, sh);
        a.z = fmaf(a.z, sc, sh); a.w = fmaf(a.w, sc, sh);
        bb.x = fmaf(bb.x, sc, sh); bb.y = fmaf(bb.y, sc, sh);
        bb.z = fmaf(bb.z, sc, sh); bb.w = fmaf(bb.w, sc, sh);
        c.x = fmaf(c.x, sc, sh); c.y = fmaf(c.y, sc, sh);
        c.z = fmaf(c.z, sc, sh); c.w = fmaf(c.w, sc, sh);
        d.x = fmaf(d.x, sc, sh); d.y = fmaf(d.y, sc, sh);
        d.z = fmaf(d.z, sc, sh); d.w = fmaf(d.w, sc, sh);
        __stcs(&ob[i], a);
        __stcs(&ob[i + TPB], bb);
        __stcs(&ob[i + 2 * TPB], c);
        __stcs(&ob[i + 3 * TPB], d);
    }
    for (; i < nvec; i += TPB) {
        float4 a = __ldcs(&xb[i]);
        a.x = fmaf(a.x, sc, sh); a.y = fmaf(a.y, sc, sh);
        a.z = fmaf(a.z, sc, sh); a.w = fmaf(a.w, sc, sh);
        __stcs(&ob[i], a);
    }
}

extern "C" void kernel_launch(void* const* d_in, const int* in_sizes, int n_in,
                              void* d_out, int out_size)
{
    const float* x     = (const float*)d_in[0];
    const float* gamma = (const float*)d_in[1];
    const float* beta  = (const float*)d_in[2];
    const int*   gs    = (const int*)d_in[3];
    float*       out   = (float*)d_out;

    const int nbatch  = in_sizes[0] / (NCHAN * HW);  // 32
    const int nblocks = nbatch * NGROUPS;            // 1024

    vgn_fused_kernel<<<nblocks, TPB>>>(x, gamma, beta, gs, out);
}